// round 1
// baseline (speedup 1.0000x reference)
#include <cuda_runtime.h>

#define CELLS_PER_BLOCK 128
#define THREADS 128
#define MAX_BLOCKS 32768

__device__ float g_partials[MAX_BLOCKS];

__global__ void __launch_bounds__(THREADS) yolo_loss_kernel(
    const float* __restrict__ pred,
    const float* __restrict__ targ,
    int total_cells)
{
    __shared__ float sp[CELLS_PER_BLOCK * 30];
    __shared__ float st[CELLS_PER_BLOCK * 30];
    __shared__ float warpsum[THREADS / 32];

    const int tid = threadIdx.x;
    const int cell0 = blockIdx.x * CELLS_PER_BLOCK;
    const int cells_here = min(CELLS_PER_BLOCK, total_cells - cell0);
    const long long base = (long long)cell0 * 30;
    const int nfloat = cells_here * 30;
    const int nvec = nfloat >> 2;

    // Coalesced float4 staging: 120B per cell, block chunk is 16B-aligned.
    const float4* p4 = reinterpret_cast<const float4*>(pred + base);
    const float4* t4 = reinterpret_cast<const float4*>(targ + base);
    float4* sp4 = reinterpret_cast<float4*>(sp);
    float4* st4 = reinterpret_cast<float4*>(st);
    for (int i = tid; i < nvec; i += THREADS) {
        sp4[i] = p4[i];
        st4[i] = t4[i];
    }
    // scalar tail (only possible on a ragged last block)
    for (int i = (nvec << 2) + tid; i < nfloat; i += THREADS) {
        sp[i] = pred[base + i];
        st[i] = targ[base + i];
    }
    __syncthreads();

    float loss = 0.0f;
    if (tid < cells_here) {
        const float* P = sp + tid * 30;
        const float* T = st + tid * 30;
        const float inv14 = 1.0f / 14.0f;

        const float conf_t = T[4];
        const float coo = (conf_t > 0.0f) ? 1.0f : 0.0f;
        const float noo = (conf_t == 0.0f) ? 1.0f : 0.0f;

        // target box -> xyxy
        const float tcx = T[0] * inv14;
        const float tcy = T[1] * inv14;
        const float tx1 = tcx - 0.5f * T[2];
        const float ty1 = tcy - 0.5f * T[3];
        const float tx2 = tcx + 0.5f * T[2];
        const float ty2 = tcy + 0.5f * T[3];
        const float ta = (tx2 - tx1) * (ty2 - ty1);

        float iou[2], bx[2], by[2], bw[2], bh[2], bc[2];
        #pragma unroll
        for (int b = 0; b < 2; b++) {
            const float* B = P + b * 5;
            bx[b] = B[0]; by[b] = B[1]; bw[b] = B[2]; bh[b] = B[3]; bc[b] = B[4];
            const float pcx = B[0] * inv14;
            const float pcy = B[1] * inv14;
            const float px1 = pcx - 0.5f * B[2];
            const float py1 = pcy - 0.5f * B[3];
            const float px2 = pcx + 0.5f * B[2];
            const float py2 = pcy + 0.5f * B[3];
            const float ltx = fmaxf(px1, tx1);
            const float lty = fmaxf(py1, ty1);
            const float rbx = fminf(px2, tx2);
            const float rby = fminf(py2, ty2);
            const float w = fmaxf(rbx - ltx, 0.0f);
            const float h = fmaxf(rby - lty, 0.0f);
            const float inter = w * h;
            const float pa = (px2 - px1) * (py2 - py1);
            iou[b] = inter / (pa + ta - inter);
        }

        // jnp.argmax picks the FIRST max -> box1 only if strictly greater
        const int r = (iou[1] > iou[0]) ? 1 : 0;
        const int nr = 1 - r;
        const float max_iou = iou[r];

        // localization loss (responsible box)
        float dx = bx[r] - T[0];
        float dy = by[r] - T[1];
        float dsw = sqrtf(bw[r]) - sqrtf(T[2]);
        float dsh = sqrtf(bh[r]) - sqrtf(T[3]);
        const float loc = dx * dx + dy * dy + dsw * dsw + dsh * dsh;

        // contain / not-contain
        const float dcc = bc[r] - max_iou;
        const float contain = dcc * dcc;
        const float ncl = bc[nr] * bc[nr];

        // no-object loss (both confidences)
        const float d4 = P[4] - T[4];
        const float d9 = P[9] - T[9];
        const float noobj = d4 * d4 + d9 * d9;

        // class loss
        float cls = 0.0f;
        #pragma unroll
        for (int k = 10; k < 30; k++) {
            const float d = P[k] - T[k];
            cls += d * d;
        }

        loss = coo * (5.0f * loc + 2.0f * contain + ncl + cls)
             + 0.5f * noo * noobj;
    }

    // warp reduce
    #pragma unroll
    for (int o = 16; o > 0; o >>= 1)
        loss += __shfl_down_sync(0xffffffffu, loss, o);
    if ((tid & 31) == 0) warpsum[tid >> 5] = loss;
    __syncthreads();
    if (tid == 0) {
        float s = 0.0f;
        #pragma unroll
        for (int w = 0; w < THREADS / 32; w++) s += warpsum[w];
        g_partials[blockIdx.x] = s;
    }
}

__global__ void __launch_bounds__(256) yolo_reduce_kernel(
    float* __restrict__ out, int nblocks, float inv_n)
{
    __shared__ float s[256];
    float acc = 0.0f;
    for (int i = threadIdx.x; i < nblocks; i += 256)
        acc += g_partials[i];
    s[threadIdx.x] = acc;
    __syncthreads();
    #pragma unroll
    for (int o = 128; o > 0; o >>= 1) {
        if (threadIdx.x < o) s[threadIdx.x] += s[threadIdx.x + o];
        __syncthreads();
    }
    if (threadIdx.x == 0) out[0] = s[0] * inv_n;
}

extern "C" void kernel_launch(void* const* d_in, const int* in_sizes, int n_in,
                              void* d_out, int out_size)
{
    const float* pred = (const float*)d_in[0];
    const float* targ = (const float*)d_in[1];
    const int total = in_sizes[0];          // N * 14 * 14 * 30
    const int cells = total / 30;
    const int N = cells / 196;              // batch size
    int blocks = (cells + CELLS_PER_BLOCK - 1) / CELLS_PER_BLOCK;
    if (blocks > MAX_BLOCKS) blocks = MAX_BLOCKS;  // safety (never hit for given shapes)

    yolo_loss_kernel<<<blocks, THREADS>>>(pred, targ, cells);
    yolo_reduce_kernel<<<1, 256>>>((float*)d_out, blocks, 1.0f / (float)N);
}